// round 9
// baseline (speedup 1.0000x reference)
#include <cuda_runtime.h>
#include <math.h>

#define NN   1024
#define EIN  4096
#define ET   5120
#define NTE  5119
#define C1   16
#define C2   7
#define INC  1433
#define WPB  8                        // warps per TE block
#define BPC  ((NTE + WPB - 1) / WPB)  // 640 blocks per channel

// ---------------- device scratch ----------------
__device__ float  g_dig[NTE + 1];
__device__ float  g_h1[NN * C1];
__device__ float  g_h2[NN * C2];
__device__ float  g_sx[C1 * NTE], g_sy[C1 * NTE], g_sz[C1 * NTE];
__device__ float  g_tesum1[C1];
__device__ float  g_tesum2[C2];
__device__ float  g_agg1[NN * C1];
__device__ float  g_agg2[NN * C2];
__device__ float  g_cnt[NN];

__device__ __forceinline__ float f_inf() { return __int_as_float(0x7f800000); }

// ---------------- init: zero accumulators + digamma table ----------------
__global__ void k_init() {
    int t = blockIdx.x * blockDim.x + threadIdx.x;
    if (t < NN * C1) g_agg1[t] = 0.f;
    if (t < NN * C2) g_agg2[t] = 0.f;
    if (t < NN)      g_cnt[t]  = 0.f;
    if (t < C1)      g_tesum1[t] = 0.f;
    if (t < C2)      g_tesum2[t] = 0.f;
    if (t <= NTE) {
        if (t == 0) { g_dig[0] = 0.f; return; }
        double x = (double)t, r = 0.0;
        while (x < 8.0) { r -= 1.0 / x; x += 1.0; }
        double ix = 1.0 / x, ix2 = ix * ix;
        r += log(x) - 0.5 * ix
           - ix2 * ((1.0/12.0) - ix2 * ((1.0/120.0) - ix2 * (1.0/252.0)));
        g_dig[t] = (float)r;
    }
}

// ---------------- layer-1 GEMM ----------------
__global__ void k_gemm1(const float* __restrict__ x,
                        const float* __restrict__ W1,
                        const float* __restrict__ b1) {
    int v    = blockIdx.x;
    int warp = threadIdx.x >> 5;
    int lane = threadIdx.x & 31;
    const float* xr = x  + (size_t)v    * INC;
    const float* wr = W1 + (size_t)warp * INC;
    float s = 0.f;
    for (int k = lane; k < INC; k += 32) s += xr[k] * wr[k];
    #pragma unroll
    for (int o = 16; o; o >>= 1) s += __shfl_xor_sync(0xffffffffu, s, o);
    if (lane == 0) g_h1[v * C1 + warp] = s + b1[warp];
}

// ------- sort samples by y: hybrid warp/shared bitonic over 1024 node values,
//         then histogram + scan + scatter of the 5119 samples -------
__global__ __launch_bounds__(1024) void k_sort(const int* __restrict__ ei, int layer) {
    __shared__ unsigned long long sk[1024];
    __shared__ int rankof[1024];
    __shared__ int cnt[1024];
    __shared__ int offs[1024];
    const int c   = blockIdx.x;
    const int tid = threadIdx.x;
    const float* h = (layer == 1) ? g_h1 : g_h2;
    const int    C = (layer == 1) ? C1 : C2;
    const unsigned FULL = 0xffffffffu;

    unsigned long long kv;
    {
        unsigned u = __float_as_uint(h[tid * C + c]);
        u = (u & 0x80000000u) ? ~u : (u | 0x80000000u);
        kv = ((unsigned long long)u << 32) | (unsigned)tid;
        cnt[tid] = 0;
    }

    // bitonic: j<32 via shuffles, j>=32 via shared
    for (int k = 2; k <= 1024; k <<= 1) {
        for (int j = k >> 1; j > 0; j >>= 1) {
            bool up = ((tid & k) == 0);
            unsigned long long other;
            if (j >= 32) {
                __syncthreads();
                sk[tid] = kv;
                __syncthreads();
                other = sk[tid ^ j];
            } else {
                other = __shfl_xor_sync(FULL, kv, j);
            }
            bool keepmin = (((tid & j) == 0) == up);
            bool swap = keepmin ? (other < kv) : (other > kv);
            if (swap) kv = other;
        }
    }
    __syncthreads();
    rankof[(int)(kv & 1023u)] = tid;
    __syncthreads();

    for (int t = tid; t < NTE; t += 1024) {
        int s0 = (t < EIN) ? ei[t] : (t - EIN);
        atomicAdd(&cnt[rankof[s0]], 1);
    }
    __syncthreads();

    int orig = cnt[tid];
    for (int off = 1; off < 1024; off <<= 1) {
        int add = (tid >= off) ? cnt[tid - off] : 0;
        __syncthreads();
        cnt[tid] += add;
        __syncthreads();
    }
    offs[tid] = cnt[tid] - orig;
    __syncthreads();

    float* SX = g_sx + (size_t)c * NTE;
    float* SY = g_sy + (size_t)c * NTE;
    float* SZ = g_sz + (size_t)c * NTE;
    for (int t = tid; t < NTE; t += 1024) {
        int s0 = (t < EIN) ? ei[t]       : (t - EIN);
        int d0 = (t < EIN) ? ei[EIN + t] : (t - EIN);
        int t1 = t + 1;
        int s1 = (t1 < EIN) ? ei[t1]     : (t1 - EIN);
        int slot = atomicAdd(&offs[rankof[s0]], 1);
        SX[slot] = h[d0 * C + c];
        SY[slot] = h[s0 * C + c];
        SZ[slot] = h[s1 * C + c];
    }
}

// ---------------- KSG TE: one warp per point, prefetched chunked scans ----------------
__global__ __launch_bounds__(32 * WPB) void k_te(int layer) {
    float* tesum = (layer == 1) ? g_tesum1 : g_tesum2;
    const int c  = blockIdx.x / BPC;
    const int bi = blockIdx.x - c * BPC;
    const int wid  = threadIdx.x >> 5;
    const int lane = threadIdx.x & 31;
    const int p    = bi * WPB + wid;
    const unsigned FULL = 0xffffffffu;

    const float* __restrict__ X = g_sx + (size_t)c * NTE;
    const float* __restrict__ Y = g_sy + (size_t)c * NTE;
    const float* __restrict__ Z = g_sz + (size_t)c * NTE;

    float val = 0.f;
    if (p < NTE) {
        float xi = X[p], yi = Y[p], zi = Z[p];

        // ======== phase A: eps (chunked, prefetched, pruned via monotone dy) ========
        float eps = f_inf();
        // ---- left ----
        if (p - 1 >= 0) {
            int jb = p - 1;
            int j = jb - lane;  bool v = (j >= 0);  int jc = v ? j : 0;
            float qy = Y[jc], qx = X[jc], qz = Z[jc];
            while (true) {
                float dy = v ? (yi - qy) : f_inf();
                float m  = v ? fmaxf(dy, fmaxf(fabsf(xi - qx), fabsf(zi - qz))) : f_inf();
                int  jbn = jb - 32;
                bool hn  = (jbn >= 0);
                int  jn  = jbn - lane;  bool vn = hn && (jn >= 0);  int jcn = vn ? jn : 0;
                float ny = 0.f, nx = 0.f, nz = 0.f;
                if (hn) { ny = Y[jcn]; nx = X[jcn]; nz = Z[jcn]; }   // prefetch
                unsigned mu = __reduce_min_sync(FULL, __float_as_uint(m));  // m >= 0
                eps = fminf(eps, __uint_as_float(mu));
                float dyf = __shfl_sync(FULL, dy, 31);
                if (!(dyf < eps) || !hn) break;
                jb = jbn; v = vn; qy = ny; qx = nx; qz = nz;
            }
        }
        // ---- right ----
        if (p + 1 < NTE) {
            int jb = p + 1;
            int j = jb + lane;  bool v = (j < NTE);  int jc = v ? j : (NTE - 1);
            float qy = Y[jc], qx = X[jc], qz = Z[jc];
            while (true) {
                float dy = v ? (qy - yi) : f_inf();
                float m  = v ? fmaxf(dy, fmaxf(fabsf(xi - qx), fabsf(zi - qz))) : f_inf();
                int  jbn = jb + 32;
                bool hn  = (jbn < NTE);
                int  jn  = jbn + lane;  bool vn = hn && (jn < NTE);  int jcn = vn ? jn : (NTE - 1);
                float ny = 0.f, nx = 0.f, nz = 0.f;
                if (hn) { ny = Y[jcn]; nx = X[jcn]; nz = Z[jcn]; }
                unsigned mu = __reduce_min_sync(FULL, __float_as_uint(m));
                eps = fminf(eps, __uint_as_float(mu));
                float dyf = __shfl_sync(FULL, dy, 31);
                if (!(dyf < eps) || !hn) break;
                jb = jbn; v = vn; qy = ny; qx = nx; qz = nz;
            }
        }

        // ======== phase B: per-lane counts over dy<eps window (self gives 1 each) ====
        int cy = (lane == 0) ? 1 : 0;
        int cxy = cy, cyz = cy;
        // ---- left ----
        if (p - 1 >= 0) {
            int jb = p - 1;
            int j = jb - lane;  bool v = (j >= 0);  int jc = v ? j : 0;
            float qy = Y[jc], qx = X[jc], qz = Z[jc];
            while (true) {
                bool in = v && ((yi - qy) < eps);
                int  jbn = jb - 32;
                bool hn  = (jbn >= 0);
                int  jn  = jbn - lane;  bool vn = hn && (jn >= 0);  int jcn = vn ? jn : 0;
                float ny = 0.f, nx = 0.f, nz = 0.f;
                if (hn) { ny = Y[jcn]; nx = X[jcn]; nz = Z[jcn]; }
                cy  += in;
                cxy += in && (fabsf(xi - qx) < eps);
                cyz += in && (fabsf(zi - qz) < eps);
                int cont = __shfl_sync(FULL, (int)in, 31);   // dy monotone: prefix window
                if (!cont || !hn) break;
                jb = jbn; v = vn; qy = ny; qx = nx; qz = nz;
            }
        }
        // ---- right ----
        if (p + 1 < NTE) {
            int jb = p + 1;
            int j = jb + lane;  bool v = (j < NTE);  int jc = v ? j : (NTE - 1);
            float qy = Y[jc], qx = X[jc], qz = Z[jc];
            while (true) {
                bool in = v && ((qy - yi) < eps);
                int  jbn = jb + 32;
                bool hn  = (jbn < NTE);
                int  jn  = jbn + lane;  bool vn = hn && (jn < NTE);  int jcn = vn ? jn : (NTE - 1);
                float ny = 0.f, nx = 0.f, nz = 0.f;
                if (hn) { ny = Y[jcn]; nx = X[jcn]; nz = Z[jcn]; }
                cy  += in;
                cxy += in && (fabsf(xi - qx) < eps);
                cyz += in && (fabsf(zi - qz) < eps);
                int cont = __shfl_sync(FULL, (int)in, 31);
                if (!cont || !hn) break;
                jb = jbn; v = vn; qy = ny; qx = nx; qz = nz;
            }
        }
        cy  = __reduce_add_sync(FULL, cy);
        cxy = __reduce_add_sync(FULL, cxy);
        cyz = __reduce_add_sync(FULL, cyz);
        val = g_dig[cy] - g_dig[cxy] - g_dig[cyz];           // warp-uniform
    }

    __shared__ float red[WPB];
    if (lane == 0) red[wid] = val;
    __syncthreads();
    if (threadIdx.x == 0) {
        float s = 0.f;
        #pragma unroll
        for (int q = 0; q < WPB; q++) s += red[q];
        atomicAdd(&tesum[c], s);
    }
}

// ---------------- aggregation ----------------
__global__ void k_agg(const int* __restrict__ ei, int layer, int C) {
    int idx = blockIdx.x * blockDim.x + threadIdx.x;
    if (idx >= ET * C) return;
    const float* h     = (layer == 1) ? g_h1 : g_h2;
    const float* tesum = (layer == 1) ? g_tesum1 : g_tesum2;
    float*       agg   = (layer == 1) ? g_agg1 : g_agg2;
    int e = idx / C, c = idx - e * C;
    int s = (e < EIN) ? ei[e]       : (e - EIN);
    int d = (e < EIN) ? ei[EIN + e] : (e - EIN);
    float tes = -0.57721566490153286f + tesum[c] * (1.0f / (float)NTE);
    if (layer == 2) tes *= 0.5f;
    float m = 1.0f / (1.0f + expf(-tes * h[s * C + c]));
    atomicAdd(&agg[d * C + c], m);
    if (layer == 1 && c == 0) atomicAdd(&g_cnt[d], 1.0f);
}

// ---------------- layer-2 GEMM ----------------
__global__ void k_gemm2(const float* __restrict__ W2, const float* __restrict__ b2) {
    int v = blockIdx.x * blockDim.x + threadIdx.x;
    if (v >= NN) return;
    float inv = 1.0f / fmaxf(g_cnt[v], 1.0f);
    float hv[C1];
    #pragma unroll
    for (int cc = 0; cc < C1; cc++) hv[cc] = fmaxf(g_agg1[v * C1 + cc] * inv, 0.0f);
    #pragma unroll
    for (int o = 0; o < C2; o++) {
        float s = b2[o];
        #pragma unroll
        for (int cc = 0; cc < C1; cc++) s += W2[o * C1 + cc] * hv[cc];
        g_h2[v * C2 + o] = s;
    }
}

// ---------------- final: mean + log_softmax ----------------
__global__ void k_final(float* __restrict__ out) {
    int v = blockIdx.x * blockDim.x + threadIdx.x;
    if (v >= NN) return;
    float inv = 1.0f / fmaxf(g_cnt[v], 1.0f);
    float val[C2], mx = -f_inf();
    #pragma unroll
    for (int o = 0; o < C2; o++) {
        val[o] = g_agg2[v * C2 + o] * inv;
        mx = fmaxf(mx, val[o]);
    }
    float s = 0.f;
    #pragma unroll
    for (int o = 0; o < C2; o++) s += expf(val[o] - mx);
    float ls = mx + logf(s);
    #pragma unroll
    for (int o = 0; o < C2; o++) out[v * C2 + o] = val[o] - ls;
}

// ---------------- launch (inputs identified by element count) ----------------
extern "C" void kernel_launch(void* const* d_in, const int* in_sizes, int n_in,
                              void* d_out, int out_size) {
    const float* x  = nullptr;
    const int*   ei = nullptr;
    const float* W1 = nullptr;
    const float* b1 = nullptr;
    const float* W2 = nullptr;
    const float* b2 = nullptr;
    for (int k = 0; k < n_in; k++) {
        switch (in_sizes[k]) {
            case NN * INC:  x  = (const float*)d_in[k]; break;
            case 2 * EIN:   ei = (const int*)  d_in[k]; break;
            case C1 * INC:  W1 = (const float*)d_in[k]; break;
            case C1:        b1 = (const float*)d_in[k]; break;
            case C2 * C1:   W2 = (const float*)d_in[k]; break;
            case C2:        b2 = (const float*)d_in[k]; break;
            default: break;
        }
    }
    float* out = (float*)d_out;

    k_init   <<<(NN * C1 + 255) / 256, 256>>>();

    // layer 1
    k_gemm1  <<<NN, 512>>>(x, W1, b1);
    k_sort   <<<C1, 1024>>>(ei, 1);
    k_te     <<<C1 * BPC, 32 * WPB>>>(1);
    k_agg    <<<(ET * C1 + 255) / 256, 256>>>(ei, 1, C1);

    // layer 2
    k_gemm2  <<<(NN + 255) / 256, 256>>>(W2, b2);
    k_sort   <<<C2, 1024>>>(ei, 2);
    k_te     <<<C2 * BPC, 32 * WPB>>>(2);
    k_agg    <<<(ET * C2 + 255) / 256, 256>>>(ei, 2, C2);

    k_final  <<<(NN + 255) / 256, 256>>>(out);
}

// round 10
// speedup vs baseline: 1.1240x; 1.1240x over previous
#include <cuda_runtime.h>
#include <math.h>

#define NN   1024
#define EIN  4096
#define ET   5120
#define NTE  5119
#define C1   16
#define C2   7
#define INC  1433
#define WPB  8                        // warps per TE block
#define BPC  ((NTE + WPB - 1) / WPB)  // 640 blocks per channel

// ---------------- device scratch ----------------
__device__ float  g_dig[NTE + 1];
__device__ float  g_h1[NN * C1];
__device__ float  g_h2[NN * C2];
__device__ float4 g_s4[C1 * NTE];
__device__ float  g_tesum1[C1];
__device__ float  g_tesum2[C2];
__device__ float  g_agg1[NN * C1];
__device__ float  g_agg2[NN * C2];
__device__ float  g_cnt[NN];

__device__ __forceinline__ float f_inf() { return __int_as_float(0x7f800000); }

// ---------------- init: zero accumulators + digamma table ----------------
__global__ void k_init() {
    int t = blockIdx.x * blockDim.x + threadIdx.x;
    if (t < NN * C1) g_agg1[t] = 0.f;
    if (t < NN * C2) g_agg2[t] = 0.f;
    if (t < NN)      g_cnt[t]  = 0.f;
    if (t < C1)      g_tesum1[t] = 0.f;
    if (t < C2)      g_tesum2[t] = 0.f;
    if (t <= NTE) {
        if (t == 0) { g_dig[0] = 0.f; return; }
        double x = (double)t, r = 0.0;
        while (x < 8.0) { r -= 1.0 / x; x += 1.0; }
        double ix = 1.0 / x, ix2 = ix * ix;
        r += log(x) - 0.5 * ix
           - ix2 * ((1.0/12.0) - ix2 * ((1.0/120.0) - ix2 * (1.0/252.0)));
        g_dig[t] = (float)r;
    }
}

// ---------------- layer-1 GEMM ----------------
__global__ void k_gemm1(const float* __restrict__ x,
                        const float* __restrict__ W1,
                        const float* __restrict__ b1) {
    int v    = blockIdx.x;
    int warp = threadIdx.x >> 5;
    int lane = threadIdx.x & 31;
    const float* xr = x  + (size_t)v    * INC;
    const float* wr = W1 + (size_t)warp * INC;
    float s = 0.f;
    for (int k = lane; k < INC; k += 32) s += xr[k] * wr[k];
    #pragma unroll
    for (int o = 16; o; o >>= 1) s += __shfl_xor_sync(0xffffffffu, s, o);
    if (lane == 0) g_h1[v * C1 + warp] = s + b1[warp];
}

// ------- sort samples by y: hybrid warp/shared bitonic over 1024 node values,
//         then histogram + scan + scatter of the 5119 samples -------
__global__ __launch_bounds__(1024) void k_sort(const int* __restrict__ ei, int layer) {
    __shared__ unsigned long long sk[1024];
    __shared__ int rankof[1024];
    __shared__ int cnt[1024];
    __shared__ int offs[1024];
    const int c   = blockIdx.x;
    const int tid = threadIdx.x;
    const float* h = (layer == 1) ? g_h1 : g_h2;
    const int    C = (layer == 1) ? C1 : C2;
    const unsigned FULL = 0xffffffffu;

    unsigned long long kv;
    {
        unsigned u = __float_as_uint(h[tid * C + c]);
        u = (u & 0x80000000u) ? ~u : (u | 0x80000000u);
        kv = ((unsigned long long)u << 32) | (unsigned)tid;
        cnt[tid] = 0;
    }

    // bitonic: j<32 via shuffles, j>=32 via shared
    for (int k = 2; k <= 1024; k <<= 1) {
        for (int j = k >> 1; j > 0; j >>= 1) {
            bool up = ((tid & k) == 0);
            unsigned long long other;
            if (j >= 32) {
                __syncthreads();
                sk[tid] = kv;
                __syncthreads();
                other = sk[tid ^ j];
            } else {
                other = __shfl_xor_sync(FULL, kv, j);
            }
            bool keepmin = (((tid & j) == 0) == up);
            bool swap = keepmin ? (other < kv) : (other > kv);
            if (swap) kv = other;
        }
    }
    __syncthreads();
    rankof[(int)(kv & 1023u)] = tid;
    __syncthreads();

    for (int t = tid; t < NTE; t += 1024) {
        int s0 = (t < EIN) ? ei[t] : (t - EIN);
        atomicAdd(&cnt[rankof[s0]], 1);
    }
    __syncthreads();

    int orig = cnt[tid];
    for (int off = 1; off < 1024; off <<= 1) {
        int add = (tid >= off) ? cnt[tid - off] : 0;
        __syncthreads();
        cnt[tid] += add;
        __syncthreads();
    }
    offs[tid] = cnt[tid] - orig;
    __syncthreads();

    float4* S = g_s4 + (size_t)c * NTE;
    for (int t = tid; t < NTE; t += 1024) {
        int s0 = (t < EIN) ? ei[t]       : (t - EIN);
        int d0 = (t < EIN) ? ei[EIN + t] : (t - EIN);
        int t1 = t + 1;
        int s1 = (t1 < EIN) ? ei[t1]     : (t1 - EIN);
        int slot = atomicAdd(&offs[rankof[s0]], 1);
        S[slot] = make_float4(h[d0 * C + c], h[s0 * C + c], h[s1 * C + c], 0.f);
    }
}

// ---------------- KSG TE: one warp per point ----------------
__global__ __launch_bounds__(32 * WPB) void k_te(int layer) {
    float* tesum = (layer == 1) ? g_tesum1 : g_tesum2;
    const int c  = blockIdx.x / BPC;
    const int bi = blockIdx.x - c * BPC;
    const int wid  = threadIdx.x >> 5;
    const int lane = threadIdx.x & 31;
    const int p    = bi * WPB + wid;
    const unsigned FULL = 0xffffffffu;

    const float4* __restrict__ S = g_s4 + (size_t)c * NTE;

    float val = 0.f;
    if (p < NTE) {
        float4 pi = S[p];
        float xi = pi.x, yi = pi.y, zi = pi.z;

        // ==== phase A: eps via ALTERNATING L/R 32-chunks (no lookahead loads) ====
        float eps = f_inf();
        int jbL = p - 1, jbR = p + 1;
        bool actL = (jbL >= 0), actR = (jbR < NTE);
        while (actL || actR) {
            if (actL) {
                int j = jbL - lane;
                bool v = (j >= 0);
                float4 q = S[v ? j : 0];
                float dy = v ? (yi - q.y) : f_inf();
                float m  = v ? fmaxf(dy, fmaxf(fabsf(xi - q.x), fabsf(zi - q.z))) : f_inf();
                unsigned mu = __reduce_min_sync(FULL, __float_as_uint(m));  // m >= 0
                eps = fminf(eps, __uint_as_float(mu));
                float dyf = __shfl_sync(FULL, dy, 31);
                jbL -= 32;
                actL = (dyf < eps) && (jbL >= 0);
            }
            if (actR) {
                int j = jbR + lane;
                bool v = (j < NTE);
                float4 q = S[v ? j : (NTE - 1)];
                float dy = v ? (q.y - yi) : f_inf();
                float m  = v ? fmaxf(dy, fmaxf(fabsf(xi - q.x), fabsf(zi - q.z))) : f_inf();
                unsigned mu = __reduce_min_sync(FULL, __float_as_uint(m));
                eps = fminf(eps, __uint_as_float(mu));
                float dyf = __shfl_sync(FULL, dy, 31);
                jbR += 32;
                actR = (dyf < eps) && (jbR < NTE);
            }
        }

        // ==== phase B: per-lane counts, 64 points per iteration (masked overscan) ====
        int cy = (lane == 0) ? 1 : 0;
        int cxy = cy, cyz = cy;
        // ---- left ----
        for (int jb = p - 1; jb >= 0; jb -= 64) {
            int j0 = jb - lane;
            bool v0 = (j0 >= 0);
            float4 q0 = S[v0 ? j0 : 0];
            int j1 = jb - 32 - lane;
            bool v1 = (j1 >= 0);
            float4 q1 = S[v1 ? j1 : 0];
            bool in0 = v0 && ((yi - q0.y) < eps);
            bool in1 = v1 && ((yi - q1.y) < eps);
            cy  += in0 + in1;
            cxy += (in0 && (fabsf(xi - q0.x) < eps)) + (in1 && (fabsf(xi - q1.x) < eps));
            cyz += (in0 && (fabsf(zi - q0.z) < eps)) + (in1 && (fabsf(zi - q1.z) < eps));
            int cont = __shfl_sync(FULL, (int)in1, 31);      // farthest of the 64
            if (!cont) break;
        }
        // ---- right ----
        for (int jb = p + 1; jb < NTE; jb += 64) {
            int j0 = jb + lane;
            bool v0 = (j0 < NTE);
            float4 q0 = S[v0 ? j0 : (NTE - 1)];
            int j1 = jb + 32 + lane;
            bool v1 = (j1 < NTE);
            float4 q1 = S[v1 ? j1 : (NTE - 1)];
            bool in0 = v0 && ((q0.y - yi) < eps);
            bool in1 = v1 && ((q1.y - yi) < eps);
            cy  += in0 + in1;
            cxy += (in0 && (fabsf(xi - q0.x) < eps)) + (in1 && (fabsf(xi - q1.x) < eps));
            cyz += (in0 && (fabsf(zi - q0.z) < eps)) + (in1 && (fabsf(zi - q1.z) < eps));
            int cont = __shfl_sync(FULL, (int)in1, 31);
            if (!cont) break;
        }
        cy  = __reduce_add_sync(FULL, cy);
        cxy = __reduce_add_sync(FULL, cxy);
        cyz = __reduce_add_sync(FULL, cyz);
        val = g_dig[cy] - g_dig[cxy] - g_dig[cyz];           // warp-uniform
    }

    __shared__ float red[WPB];
    if (lane == 0) red[wid] = val;
    __syncthreads();
    if (threadIdx.x == 0) {
        float s = 0.f;
        #pragma unroll
        for (int q = 0; q < WPB; q++) s += red[q];
        atomicAdd(&tesum[c], s);
    }
}

// ---------------- aggregation ----------------
__global__ void k_agg(const int* __restrict__ ei, int layer, int C) {
    int idx = blockIdx.x * blockDim.x + threadIdx.x;
    if (idx >= ET * C) return;
    const float* h     = (layer == 1) ? g_h1 : g_h2;
    const float* tesum = (layer == 1) ? g_tesum1 : g_tesum2;
    float*       agg   = (layer == 1) ? g_agg1 : g_agg2;
    int e = idx / C, c = idx - e * C;
    int s = (e < EIN) ? ei[e]       : (e - EIN);
    int d = (e < EIN) ? ei[EIN + e] : (e - EIN);
    float tes = -0.57721566490153286f + tesum[c] * (1.0f / (float)NTE);
    if (layer == 2) tes *= 0.5f;
    float m = 1.0f / (1.0f + expf(-tes * h[s * C + c]));
    atomicAdd(&agg[d * C + c], m);
    if (layer == 1 && c == 0) atomicAdd(&g_cnt[d], 1.0f);
}

// ---------------- layer-2 GEMM ----------------
__global__ void k_gemm2(const float* __restrict__ W2, const float* __restrict__ b2) {
    int v = blockIdx.x * blockDim.x + threadIdx.x;
    if (v >= NN) return;
    float inv = 1.0f / fmaxf(g_cnt[v], 1.0f);
    float hv[C1];
    #pragma unroll
    for (int cc = 0; cc < C1; cc++) hv[cc] = fmaxf(g_agg1[v * C1 + cc] * inv, 0.0f);
    #pragma unroll
    for (int o = 0; o < C2; o++) {
        float s = b2[o];
        #pragma unroll
        for (int cc = 0; cc < C1; cc++) s += W2[o * C1 + cc] * hv[cc];
        g_h2[v * C2 + o] = s;
    }
}

// ---------------- final: mean + log_softmax ----------------
__global__ void k_final(float* __restrict__ out) {
    int v = blockIdx.x * blockDim.x + threadIdx.x;
    if (v >= NN) return;
    float inv = 1.0f / fmaxf(g_cnt[v], 1.0f);
    float val[C2], mx = -f_inf();
    #pragma unroll
    for (int o = 0; o < C2; o++) {
        val[o] = g_agg2[v * C2 + o] * inv;
        mx = fmaxf(mx, val[o]);
    }
    float s = 0.f;
    #pragma unroll
    for (int o = 0; o < C2; o++) s += expf(val[o] - mx);
    float ls = mx + logf(s);
    #pragma unroll
    for (int o = 0; o < C2; o++) out[v * C2 + o] = val[o] - ls;
}

// ---------------- launch (inputs identified by element count) ----------------
extern "C" void kernel_launch(void* const* d_in, const int* in_sizes, int n_in,
                              void* d_out, int out_size) {
    const float* x  = nullptr;
    const int*   ei = nullptr;
    const float* W1 = nullptr;
    const float* b1 = nullptr;
    const float* W2 = nullptr;
    const float* b2 = nullptr;
    for (int k = 0; k < n_in; k++) {
        switch (in_sizes[k]) {
            case NN * INC:  x  = (const float*)d_in[k]; break;
            case 2 * EIN:   ei = (const int*)  d_in[k]; break;
            case C1 * INC:  W1 = (const float*)d_in[k]; break;
            case C1:        b1 = (const float*)d_in[k]; break;
            case C2 * C1:   W2 = (const float*)d_in[k]; break;
            case C2:        b2 = (const float*)d_in[k]; break;
            default: break;
        }
    }
    float* out = (float*)d_out;

    k_init   <<<(NN * C1 + 255) / 256, 256>>>();

    // layer 1
    k_gemm1  <<<NN, 512>>>(x, W1, b1);
    k_sort   <<<C1, 1024>>>(ei, 1);
    k_te     <<<C1 * BPC, 32 * WPB>>>(1);
    k_agg    <<<(ET * C1 + 255) / 256, 256>>>(ei, 1, C1);

    // layer 2
    k_gemm2  <<<(NN + 255) / 256, 256>>>(W2, b2);
    k_sort   <<<C2, 1024>>>(ei, 2);
    k_te     <<<C2 * BPC, 32 * WPB>>>(2);
    k_agg    <<<(ET * C2 + 255) / 256, 256>>>(ei, 2, C2);

    k_final  <<<(NN + 255) / 256, 256>>>(out);
}